// round 15
// baseline (speedup 1.0000x reference)
#include <cuda_runtime.h>
#include <cstdint>

#define FDIM 2048
#define BATCH 64
#define LOG2E 1.4426950408889634f
#define NSPLIT 4
#define NBINS 128
#define NCHK 4                          // j-chunks per batch row (512 j each)
#define ITILE 4                         // i's per thread in attn2
#define NGRP 4                          // bin-split groups in attn2
#define BINS_PER_GRP (NBINS / NGRP)     // 32
#define KMIN_R (-7.0f)
#define RANGE_R 14.0f
#define DLT (RANGE_R / NBINS)
#define INVD (NBINS / RANGE_R)
#define C1T 0.69314718056f     // ln2
#define C2T 0.24022650696f     // ln2^2/2
#define C3T 0.05550410866f     // ln2^3/6

// K-split partial results: g_part[ksplit][0=q,1=k,2=v][b*F]
__device__ float g_part[NSPLIT][3][BATCH * FDIM];

// per-(b,chunk) private bin slices + merged tables; overwritten every call
__device__ float4 g_sliceA[BATCH][NCHK][NBINS];
__device__ float4 g_sliceB[BATCH][NCHK][NBINS];
__device__ float4 g_mergeA[BATCH][NBINS];
__device__ float4 g_mergeB[BATCH][NBINS];

// split a,b into bf16 hi pair + bf16 lo (residual) pair; a = low half
__device__ __forceinline__ void cvt_split(float a, float b, uint32_t& hi, uint32_t& lo) {
    uint32_t h;
    asm("cvt.rn.bf16x2.f32 %0, %1, %2;" : "=r"(h) : "f"(b), "f"(a));
    float ra = __uint_as_float(h << 16);
    float rb = __uint_as_float(h & 0xffff0000u);
    asm("cvt.rn.bf16x2.f32 %0, %1, %2;" : "=r"(lo) : "f"(b - rb), "f"(a - ra));
    hi = h;
}

__device__ __forceinline__ void mma16816(float* c, const uint32_t* a, uint32_t b0, uint32_t b1) {
    asm volatile("mma.sync.aligned.m16n8k16.row.col.f32.bf16.bf16.f32 "
        "{%0,%1,%2,%3}, {%4,%5,%6,%7}, {%8,%9}, {%0,%1,%2,%3};"
        : "+f"(c[0]), "+f"(c[1]), "+f"(c[2]), "+f"(c[3])
        : "r"(a[0]), "r"(a[1]), "r"(a[2]), "r"(a[3]), "r"(b0), "r"(b1));
}

__device__ __forceinline__ void cpa16(uint32_t dst, const void* src) {
    asm volatile("cp.async.cg.shared.global [%0], [%1], 16;" :: "r"(dst), "l"(src));
}

// ============================================================
// Phase 1: warp-MMA GEMM (best measured config).
// bf16 error-split (hh+hl+lh), 4-stage cp.async fp32 ring,
// wait_group 2, fragments via direct LDS.128 + in-reg convert.
// Block tile M=64 x N=64, K-chunk 32, K-split 4. grid 384.
// ============================================================
#define SPITCH 48
#define STG_ARR (64 * SPITCH * 4)
#define STG_PAIR (2 * STG_ARR)
#define NSTAGE 4
#define GEMM_SMEM (NSTAGE * STG_PAIR)  // 98304 B

__global__ __launch_bounds__(256, 2) void gemm_mma(
    const float* __restrict__ x,
    const float* __restrict__ Wq,
    const float* __restrict__ Wk,
    const float* __restrict__ Wv)
{
    extern __shared__ char smem[];
    const uint32_t sb = (uint32_t)__cvta_generic_to_shared(smem);

    const int tid  = threadIdx.x;
    const int wid  = tid >> 5;
    const int lane = tid & 31;

    const int bx   = blockIdx.x;
    const int ks   = bx & 3;
    const int nt   = (bx >> 2) & 31;
    const int wsel = bx >> 7;
    const float* __restrict__ W = (wsel == 0) ? Wq : ((wsel == 1) ? Wk : Wv);
    float* __restrict__ outp = g_part[ks][wsel];
    const int k0 = ks * 512;
    const int n0 = nt * 64;

    const int wm = wid >> 1;
    const int wn = wid & 1;
    const int gid  = lane >> 2;
    const int tidq = lane & 3;

    const int lrow = tid >> 3;
    const int lc16 = tid & 7;
    const float* xsrc0 = x + lrow * FDIM + k0 + lc16 * 4;
    const float* xsrc1 = xsrc0 + 32 * FDIM;
    const float* wsrc0 = W + (n0 + lrow) * FDIM + k0 + lc16 * 4;
    const float* wsrc1 = wsrc0 + 32 * FDIM;
    const uint32_t xdst0 = sb + lrow * 192 + lc16 * 16;
    const uint32_t xdst1 = xdst0 + 32 * 192;
    const uint32_t wdst0 = xdst0 + STG_ARR;
    const uint32_t wdst1 = wdst0 + 32 * 192;

    float acc[4][4];
#pragma unroll
    for (int i = 0; i < 4; i++)
#pragma unroll
        for (int j = 0; j < 4; j++) acc[i][j] = 0.0f;

    const uint32_t a_base = (uint32_t)((wm * 16 + gid) * 192 + tidq * 16);
    const uint32_t b_base = (uint32_t)(STG_ARR + (wn * 32 + gid) * 192 + tidq * 16);

#pragma unroll
    for (int pc = 0; pc < NSTAGE - 1; pc++) {
        const uint32_t so = pc * STG_PAIR;
        const int kf = pc * 32;
        cpa16(so + xdst0, xsrc0 + kf);
        cpa16(so + xdst1, xsrc1 + kf);
        cpa16(so + wdst0, wsrc0 + kf);
        cpa16(so + wdst1, wsrc1 + kf);
        asm volatile("cp.async.commit_group;" ::: "memory");
    }

    for (int c = 0; c < 16; c++) {
        asm volatile("cp.async.wait_group 2;" ::: "memory");
        __syncthreads();

        const int nc = c + NSTAGE - 1;
        if (nc < 16) {
            const uint32_t so = (nc & (NSTAGE - 1)) * STG_PAIR;
            const int kf = nc * 32;
            cpa16(so + xdst0, xsrc0 + kf);
            cpa16(so + xdst1, xsrc1 + kf);
            cpa16(so + wdst0, wsrc0 + kf);
            cpa16(so + wdst1, wsrc1 + kf);
        }
        asm volatile("cp.async.commit_group;" ::: "memory");

        const uint32_t slot = (c & (NSTAGE - 1)) * STG_PAIR;
        const uint32_t aa = sb + slot + a_base;
        const uint32_t bb = sb + slot + b_base;

#pragma unroll
        for (int kstep = 0; kstep < 2; kstep++) {
            const uint32_t kb = kstep * 64;
            float4 A0, A1;
            asm volatile("ld.shared.v4.f32 {%0,%1,%2,%3}, [%4];"
                : "=f"(A0.x), "=f"(A0.y), "=f"(A0.z), "=f"(A0.w) : "r"(aa + kb));
            asm volatile("ld.shared.v4.f32 {%0,%1,%2,%3}, [%4];"
                : "=f"(A1.x), "=f"(A1.y), "=f"(A1.z), "=f"(A1.w) : "r"(aa + kb + 8 * 192));
            uint32_t ah[4], al[4];
            cvt_split(A0.x, A0.y, ah[0], al[0]);
            cvt_split(A1.x, A1.y, ah[1], al[1]);
            cvt_split(A0.z, A0.w, ah[2], al[2]);
            cvt_split(A1.z, A1.w, ah[3], al[3]);

#pragma unroll
            for (int t = 0; t < 4; t++) {
                float4 B;
                asm volatile("ld.shared.v4.f32 {%0,%1,%2,%3}, [%4];"
                    : "=f"(B.x), "=f"(B.y), "=f"(B.z), "=f"(B.w)
                    : "r"(bb + kb + t * 8 * 192));
                uint32_t bh0, bh1, bl0, bl1;
                cvt_split(B.x, B.y, bh0, bl0);
                cvt_split(B.z, B.w, bh1, bl1);
                mma16816(acc[t], ah, bh0, bh1);    // hh
                mma16816(acc[t], ah, bl0, bl1);    // hl
                mma16816(acc[t], al, bh0, bh1);    // lh
            }
        }
    }

    const int orow = wm * 16 + (lane >> 2);
    const int ocol = n0 + wn * 32 + (lane & 3) * 2;
#pragma unroll
    for (int t = 0; t < 4; t++) {
        const int col = ocol + t * 8;
        *(float2*)&outp[orow * FDIM + col]       = make_float2(acc[t][0], acc[t][1]);
        *(float2*)&outp[(orow + 8) * FDIM + col] = make_float2(acc[t][2], acc[t][3]);
    }
}

// ============================================================
// Phase 2a: parallel binning, grid (NCHK, BATCH), 512 threads.
// ============================================================
__global__ __launch_bounds__(512) void binprep(const int* __restrict__ mask)
{
    __shared__ __align__(16) float4 sA[NBINS];
    __shared__ __align__(16) float4 sB[NBINS];

    const int b   = blockIdx.y;
    const int ch  = blockIdx.x;
    const int tid = threadIdx.x;
    const int off = b * FDIM;
    const int j   = ch * 512 + tid;

    if (tid < NBINS) {
        sA[tid] = make_float4(0.f, 0.f, 0.f, 0.f);
        sB[tid] = make_float4(0.f, 0.f, 0.f, 0.f);
    }
    __syncthreads();

    const int m = mask[off + j];
    if (m) {
        float kv = 0.0f, vv = 0.0f;
#pragma unroll
        for (int sp = 0; sp < NSPLIT; sp++) {
            kv += g_part[sp][1][off + j];
            vv += g_part[sp][2][off + j];
        }
        int bi = (int)((kv - KMIN_R) * INVD);
        bi = bi < 0 ? 0 : (bi > NBINS - 1 ? NBINS - 1 : bi);
        const float d  = kv - (KMIN_R + (bi + 0.5f) * DLT);
        const float d1 = C1T * d;
        const float d2 = C2T * d * d;
        const float d3 = C3T * d * d * d;
        atomicAdd(&sA[bi].x, 1.0f);
        atomicAdd(&sA[bi].y, vv);
        atomicAdd(&sA[bi].z, d1);
        atomicAdd(&sA[bi].w, d1 * vv);
        atomicAdd(&sB[bi].x, d2);
        atomicAdd(&sB[bi].y, d2 * vv);
        atomicAdd(&sB[bi].z, d3);
        atomicAdd(&sB[bi].w, d3 * vv);
    }
    __syncthreads();

    if (tid < NBINS) {
        g_sliceA[b][ch][tid] = sA[tid];
        g_sliceB[b][ch][tid] = sB[tid];
    }
}

// ============================================================
// Phase 2a': merge slices once per (b, bin). grid 64 x 128 thr.
// ============================================================
__global__ __launch_bounds__(NBINS) void binmerge()
{
    const int b = blockIdx.x;
    const int t = threadIdx.x;
    float4 a = make_float4(0.f, 0.f, 0.f, 0.f);
    float4 bb = make_float4(0.f, 0.f, 0.f, 0.f);
#pragma unroll
    for (int ch = 0; ch < NCHK; ch++) {
        float4 va = g_sliceA[b][ch][t];
        float4 vb = g_sliceB[b][ch][t];
        a.x += va.x; a.y += va.y; a.z += va.z; a.w += va.w;
        bb.x += vb.x; bb.y += vb.y; bb.z += vb.z; bb.w += vb.w;
    }
    g_mergeA[b][t] = a;
    g_mergeB[b][t] = bb;
}

// ============================================================
// Phase 2b: attended[b,i]. 512 threads = 4 groups x 128 lanes;
// group g handles bins [32g, 32g+32) for the same ITILE=4 i's
// (4x thread count vs R14 -> latency hidden). Estrin form:
// H = (S0 + qs*S1) + qs^2*(S2 + qs*S3), depth-2 FFMA2 chain.
// Group partials merged via smem; group 0 divides and stores.
// ============================================================
__global__ __launch_bounds__(512) void attn2(float* __restrict__ out)
{
    __shared__ __align__(16) float4 sAA[NBINS];
    __shared__ __align__(16) float4 sBB[NBINS];
    __shared__ unsigned long long red[NGRP - 1][128][ITILE];

    const int b   = blockIdx.y;
    const int tid = threadIdx.x;
    const int grp = tid >> 7;
    const int lt  = tid & 127;
    const int off = b * FDIM;

    if (tid < NBINS) {
        sAA[tid] = g_mergeA[b][tid];
        sBB[tid] = g_mergeB[b][tid];
    }
    __syncthreads();

    const int i0 = blockIdx.x * (128 * ITILE) + lt;

    float qs[ITILE], negm[ITILE];
    unsigned long long qs2[ITILE], qsq2[ITILE], acc[ITILE];
#pragma unroll
    for (int s = 0; s < ITILE; s++) {
        float qraw = 0.0f;
#pragma unroll
        for (int sp = 0; sp < NSPLIT; sp++) qraw += g_part[sp][0][off + i0 + s * 128];
        qs[s]   = qraw * LOG2E;
        negm[s] = -7.0f * fabsf(qs[s]);
        const float qq = qs[s] * qs[s];
        asm("mov.b64 %0, {%1, %1};" : "=l"(qs2[s])  : "r"(__float_as_uint(qs[s])));
        asm("mov.b64 %0, {%1, %1};" : "=l"(qsq2[s]) : "r"(__float_as_uint(qq)));
        acc[s] = 0ull;
    }

    const int pbase = grp * BINS_PER_GRP;
    float kc = KMIN_R + (pbase + 0.5f) * DLT;
#pragma unroll 2
    for (int p = 0; p < BINS_PER_GRP; p++) {
        ulonglong2 A = *(const ulonglong2*)&sAA[pbase + p];
        ulonglong2 B = *(const ulonglong2*)&sBB[pbase + p];
#pragma unroll
        for (int s = 0; s < ITILE; s++) {
            float t = fmaf(qs[s], kc, negm[s]);
            float e;
            asm("ex2.approx.ftz.f32 %0, %1;" : "=f"(e) : "f"(t));
            unsigned long long e2, T1, T2, H;
            asm("mov.b64 %0, {%1, %1};" : "=l"(e2) : "r"(__float_as_uint(e)));
            asm("fma.rn.f32x2 %0, %1, %2, %3;" : "=l"(T1) : "l"(qs2[s]),  "l"(A.y), "l"(A.x));
            asm("fma.rn.f32x2 %0, %1, %2, %3;" : "=l"(T2) : "l"(qs2[s]),  "l"(B.y), "l"(B.x));
            asm("fma.rn.f32x2 %0, %1, %2, %3;" : "=l"(H)  : "l"(qsq2[s]), "l"(T2),  "l"(T1));
            asm("fma.rn.f32x2 %0, %1, %2, %0;" : "+l"(acc[s]) : "l"(e2), "l"(H));
        }
        kc += DLT;
    }

    if (grp > 0) {
#pragma unroll
        for (int s = 0; s < ITILE; s++) red[grp - 1][lt][s] = acc[s];
    }
    __syncthreads();

    if (grp == 0) {
#pragma unroll
        for (int s = 0; s < ITILE; s++) {
            unsigned long long t = acc[s];
#pragma unroll
            for (int g = 0; g < NGRP - 1; g++) {
                asm("add.rn.f32x2 %0, %0, %1;" : "+l"(t) : "l"(red[g][lt][s]));
            }
            unsigned int dlo, dhi;
            asm("mov.b64 {%0, %1}, %2;" : "=r"(dlo), "=r"(dhi) : "l"(t));
            out[off + i0 + s * 128] = __uint_as_float(dhi) / __uint_as_float(dlo);
        }
    }
}

extern "C" void kernel_launch(void* const* d_in, const int* in_sizes, int n_in,
                              void* d_out, int out_size)
{
    const float* x    = (const float*)d_in[0];
    const int*   mask = (const int*)d_in[1];
    const float* Wq   = (const float*)d_in[2];
    const float* Wk   = (const float*)d_in[3];
    const float* Wv   = (const float*)d_in[4];
    float* out = (float*)d_out;

    cudaFuncSetAttribute(gemm_mma, cudaFuncAttributeMaxDynamicSharedMemorySize, GEMM_SMEM);
    gemm_mma<<<384, 256, GEMM_SMEM>>>(x, Wq, Wk, Wv);
    binprep<<<dim3(NCHK, BATCH), 512>>>(mask);
    binmerge<<<BATCH, NBINS>>>();
    attn2<<<dim3(FDIM / (128 * ITILE), BATCH), 512>>>(out);
}

// round 16
// speedup vs baseline: 1.1113x; 1.1113x over previous
#include <cuda_runtime.h>
#include <cuda_fp16.h>
#include <cstdint>

#define FDIM 2048
#define BATCH 64
#define LOG2E 1.4426950408889634f
#define NSPLIT 4
#define NBINS 128
#define NCHK 4                          // j-chunks per batch row (512 j each)
#define ITILE 4                         // i's per thread in attn2
#define NGRP 4                          // bin-split groups in attn2
#define LANES 64                        // lanes per group in attn2
#define BINS_PER_GRP (NBINS / NGRP)     // 32
#define KMIN_R (-7.0f)
#define RANGE_R 14.0f
#define DLT (RANGE_R / NBINS)
#define INVD (NBINS / RANGE_R)
#define C1T 0.69314718056f     // ln2
#define C2T 0.24022650696f     // ln2^2/2
#define C3T 0.05550410866f     // ln2^3/6

// K-split partial results: g_part[ksplit][0=q,1=k,2=v][b*F]
__device__ float g_part[NSPLIT][3][BATCH * FDIM];

// per-(b,chunk) private bin slices + merged tables; overwritten every call
__device__ float4 g_sliceA[BATCH][NCHK][NBINS];
__device__ float4 g_sliceB[BATCH][NCHK][NBINS];
__device__ float4 g_mergeA[BATCH][NBINS];
__device__ float4 g_mergeB[BATCH][NBINS];

// split a,b into fp16 hi pair + fp16 lo (residual) pair; a = low half
__device__ __forceinline__ void cvt_split_f16(float a, float b, uint32_t& hi, uint32_t& lo) {
    uint32_t h;
    asm("cvt.rn.f16x2.f32 %0, %1, %2;" : "=r"(h) : "f"(b), "f"(a));
    float2 hf = __half22float2(*(__half2*)&h);   // .x = a-half, .y = b-half
    float la = a - hf.x;
    float lb = b - hf.y;
    asm("cvt.rn.f16x2.f32 %0, %1, %2;" : "=r"(lo) : "f"(lb), "f"(la));
    hi = h;
}

__device__ __forceinline__ uint32_t cvt_f16x2(float a, float b) {
    uint32_t h;
    asm("cvt.rn.f16x2.f32 %0, %1, %2;" : "=r"(h) : "f"(b), "f"(a));
    return h;
}

__device__ __forceinline__ void mma16816f16(float* c, const uint32_t* a, uint32_t b0, uint32_t b1) {
    asm volatile("mma.sync.aligned.m16n8k16.row.col.f32.f16.f16.f32 "
        "{%0,%1,%2,%3}, {%4,%5,%6,%7}, {%8,%9}, {%0,%1,%2,%3};"
        : "+f"(c[0]), "+f"(c[1]), "+f"(c[2]), "+f"(c[3])
        : "r"(a[0]), "r"(a[1]), "r"(a[2]), "r"(a[3]), "r"(b0), "r"(b1));
}

__device__ __forceinline__ void cpa16(uint32_t dst, const void* src) {
    asm volatile("cp.async.cg.shared.global [%0], [%1], 16;" :: "r"(dst), "l"(src));
}

// ============================================================
// Phase 1: warp-MMA GEMM, fp16 asymmetric 2-product split:
// x = xh + xl (fp16), W = fp16 plain; score = xh*W + xl*W.
// Omitted term x*w_lo ~ 3e-4 abs on unit-variance scores.
// 4-stage cp.async fp32 ring, wait_group 2, direct LDS.128 +
// in-register convert. Tile M=64 x N=64, K-chunk 32. grid 384.
// ============================================================
#define SPITCH 48
#define STG_ARR (64 * SPITCH * 4)
#define STG_PAIR (2 * STG_ARR)
#define NSTAGE 4
#define GEMM_SMEM (NSTAGE * STG_PAIR)  // 98304 B

__global__ __launch_bounds__(256, 2) void gemm_mma(
    const float* __restrict__ x,
    const float* __restrict__ Wq,
    const float* __restrict__ Wk,
    const float* __restrict__ Wv)
{
    extern __shared__ char smem[];
    const uint32_t sb = (uint32_t)__cvta_generic_to_shared(smem);

    const int tid  = threadIdx.x;
    const int wid  = tid >> 5;
    const int lane = tid & 31;

    const int bx   = blockIdx.x;
    const int ks   = bx & 3;
    const int nt   = (bx >> 2) & 31;
    const int wsel = bx >> 7;
    const float* __restrict__ W = (wsel == 0) ? Wq : ((wsel == 1) ? Wk : Wv);
    float* __restrict__ outp = g_part[ks][wsel];
    const int k0 = ks * 512;
    const int n0 = nt * 64;

    const int wm = wid >> 1;
    const int wn = wid & 1;
    const int gid  = lane >> 2;
    const int tidq = lane & 3;

    const int lrow = tid >> 3;
    const int lc16 = tid & 7;
    const float* xsrc0 = x + lrow * FDIM + k0 + lc16 * 4;
    const float* xsrc1 = xsrc0 + 32 * FDIM;
    const float* wsrc0 = W + (n0 + lrow) * FDIM + k0 + lc16 * 4;
    const float* wsrc1 = wsrc0 + 32 * FDIM;
    const uint32_t xdst0 = sb + lrow * 192 + lc16 * 16;
    const uint32_t xdst1 = xdst0 + 32 * 192;
    const uint32_t wdst0 = xdst0 + STG_ARR;
    const uint32_t wdst1 = wdst0 + 32 * 192;

    float acc[4][4];
#pragma unroll
    for (int i = 0; i < 4; i++)
#pragma unroll
        for (int j = 0; j < 4; j++) acc[i][j] = 0.0f;

    const uint32_t a_base = (uint32_t)((wm * 16 + gid) * 192 + tidq * 16);
    const uint32_t b_base = (uint32_t)(STG_ARR + (wn * 32 + gid) * 192 + tidq * 16);

#pragma unroll
    for (int pc = 0; pc < NSTAGE - 1; pc++) {
        const uint32_t so = pc * STG_PAIR;
        const int kf = pc * 32;
        cpa16(so + xdst0, xsrc0 + kf);
        cpa16(so + xdst1, xsrc1 + kf);
        cpa16(so + wdst0, wsrc0 + kf);
        cpa16(so + wdst1, wsrc1 + kf);
        asm volatile("cp.async.commit_group;" ::: "memory");
    }

    for (int c = 0; c < 16; c++) {
        asm volatile("cp.async.wait_group 2;" ::: "memory");
        __syncthreads();

        const int nc = c + NSTAGE - 1;
        if (nc < 16) {
            const uint32_t so = (nc & (NSTAGE - 1)) * STG_PAIR;
            const int kf = nc * 32;
            cpa16(so + xdst0, xsrc0 + kf);
            cpa16(so + xdst1, xsrc1 + kf);
            cpa16(so + wdst0, wsrc0 + kf);
            cpa16(so + wdst1, wsrc1 + kf);
        }
        asm volatile("cp.async.commit_group;" ::: "memory");

        const uint32_t slot = (c & (NSTAGE - 1)) * STG_PAIR;
        const uint32_t aa = sb + slot + a_base;
        const uint32_t bb = sb + slot + b_base;

#pragma unroll
        for (int kstep = 0; kstep < 2; kstep++) {
            const uint32_t kb = kstep * 64;
            float4 A0, A1;
            asm volatile("ld.shared.v4.f32 {%0,%1,%2,%3}, [%4];"
                : "=f"(A0.x), "=f"(A0.y), "=f"(A0.z), "=f"(A0.w) : "r"(aa + kb));
            asm volatile("ld.shared.v4.f32 {%0,%1,%2,%3}, [%4];"
                : "=f"(A1.x), "=f"(A1.y), "=f"(A1.z), "=f"(A1.w) : "r"(aa + kb + 8 * 192));
            uint32_t ah[4], al[4];
            cvt_split_f16(A0.x, A0.y, ah[0], al[0]);
            cvt_split_f16(A1.x, A1.y, ah[1], al[1]);
            cvt_split_f16(A0.z, A0.w, ah[2], al[2]);
            cvt_split_f16(A1.z, A1.w, ah[3], al[3]);

#pragma unroll
            for (int t = 0; t < 4; t++) {
                float4 B;
                asm volatile("ld.shared.v4.f32 {%0,%1,%2,%3}, [%4];"
                    : "=f"(B.x), "=f"(B.y), "=f"(B.z), "=f"(B.w)
                    : "r"(bb + kb + t * 8 * 192));
                const uint32_t b0 = cvt_f16x2(B.x, B.y);
                const uint32_t b1 = cvt_f16x2(B.z, B.w);
                mma16816f16(acc[t], ah, b0, b1);    // xh * W
                mma16816f16(acc[t], al, b0, b1);    // xl * W
            }
        }
    }

    const int orow = wm * 16 + (lane >> 2);
    const int ocol = n0 + wn * 32 + (lane & 3) * 2;
#pragma unroll
    for (int t = 0; t < 4; t++) {
        const int col = ocol + t * 8;
        *(float2*)&outp[orow * FDIM + col]       = make_float2(acc[t][0], acc[t][1]);
        *(float2*)&outp[(orow + 8) * FDIM + col] = make_float2(acc[t][2], acc[t][3]);
    }
}

// ============================================================
// Phase 2a: parallel binning, grid (NCHK, BATCH), 512 threads.
// ============================================================
__global__ __launch_bounds__(512) void binprep(const int* __restrict__ mask)
{
    __shared__ __align__(16) float4 sA[NBINS];
    __shared__ __align__(16) float4 sB[NBINS];

    const int b   = blockIdx.y;
    const int ch  = blockIdx.x;
    const int tid = threadIdx.x;
    const int off = b * FDIM;
    const int j   = ch * 512 + tid;

    if (tid < NBINS) {
        sA[tid] = make_float4(0.f, 0.f, 0.f, 0.f);
        sB[tid] = make_float4(0.f, 0.f, 0.f, 0.f);
    }
    __syncthreads();

    const int m = mask[off + j];
    if (m) {
        float kv = 0.0f, vv = 0.0f;
#pragma unroll
        for (int sp = 0; sp < NSPLIT; sp++) {
            kv += g_part[sp][1][off + j];
            vv += g_part[sp][2][off + j];
        }
        int bi = (int)((kv - KMIN_R) * INVD);
        bi = bi < 0 ? 0 : (bi > NBINS - 1 ? NBINS - 1 : bi);
        const float d  = kv - (KMIN_R + (bi + 0.5f) * DLT);
        const float d1 = C1T * d;
        const float d2 = C2T * d * d;
        const float d3 = C3T * d * d * d;
        atomicAdd(&sA[bi].x, 1.0f);
        atomicAdd(&sA[bi].y, vv);
        atomicAdd(&sA[bi].z, d1);
        atomicAdd(&sA[bi].w, d1 * vv);
        atomicAdd(&sB[bi].x, d2);
        atomicAdd(&sB[bi].y, d2 * vv);
        atomicAdd(&sB[bi].z, d3);
        atomicAdd(&sB[bi].w, d3 * vv);
    }
    __syncthreads();

    if (tid < NBINS) {
        g_sliceA[b][ch][tid] = sA[tid];
        g_sliceB[b][ch][tid] = sB[tid];
    }
}

// ============================================================
// Phase 2a': merge slices once per (b, bin). grid 64 x 128 thr.
// ============================================================
__global__ __launch_bounds__(NBINS) void binmerge()
{
    const int b = blockIdx.x;
    const int t = threadIdx.x;
    float4 a = make_float4(0.f, 0.f, 0.f, 0.f);
    float4 bb = make_float4(0.f, 0.f, 0.f, 0.f);
#pragma unroll
    for (int ch = 0; ch < NCHK; ch++) {
        float4 va = g_sliceA[b][ch][t];
        float4 vb = g_sliceB[b][ch][t];
        a.x += va.x; a.y += va.y; a.z += va.z; a.w += va.w;
        bb.x += vb.x; bb.y += vb.y; bb.z += vb.z; bb.w += vb.w;
    }
    g_mergeA[b][t] = a;
    g_mergeB[b][t] = bb;
}

// ============================================================
// Phase 2b: attended[b,i]. 256 threads = 4 groups x 64 lanes;
// group g handles bins [32g, 32g+32) for the same ITILE=4 i's.
// grid (8, 64) = 512 blocks -> balanced waves (1.16 overhead).
// Estrin: H = (S0 + qs*S1) + qs^2*(S2 + qs*S3); packed f32x2.
// ============================================================
__global__ __launch_bounds__(NGRP * LANES) void attn2(float* __restrict__ out)
{
    __shared__ __align__(16) float4 sAA[NBINS];
    __shared__ __align__(16) float4 sBB[NBINS];
    __shared__ unsigned long long red[NGRP - 1][LANES][ITILE];

    const int b   = blockIdx.y;
    const int tid = threadIdx.x;
    const int grp = tid / LANES;
    const int lt  = tid % LANES;
    const int off = b * FDIM;

    if (tid < NBINS) {
        sAA[tid] = g_mergeA[b][tid];
        sBB[tid] = g_mergeB[b][tid];
    }
    __syncthreads();

    const int i0 = blockIdx.x * (LANES * ITILE) + lt;

    float qs[ITILE], negm[ITILE];
    unsigned long long qs2[ITILE], qsq2[ITILE], acc[ITILE];
#pragma unroll
    for (int s = 0; s < ITILE; s++) {
        float qraw = 0.0f;
#pragma unroll
        for (int sp = 0; sp < NSPLIT; sp++) qraw += g_part[sp][0][off + i0 + s * LANES];
        qs[s]   = qraw * LOG2E;
        negm[s] = -7.0f * fabsf(qs[s]);
        const float qq = qs[s] * qs[s];
        asm("mov.b64 %0, {%1, %1};" : "=l"(qs2[s])  : "r"(__float_as_uint(qs[s])));
        asm("mov.b64 %0, {%1, %1};" : "=l"(qsq2[s]) : "r"(__float_as_uint(qq)));
        acc[s] = 0ull;
    }

    const int pbase = grp * BINS_PER_GRP;
    float kc = KMIN_R + (pbase + 0.5f) * DLT;
#pragma unroll 2
    for (int p = 0; p < BINS_PER_GRP; p++) {
        ulonglong2 A = *(const ulonglong2*)&sAA[pbase + p];
        ulonglong2 B = *(const ulonglong2*)&sBB[pbase + p];
#pragma unroll
        for (int s = 0; s < ITILE; s++) {
            float t = fmaf(qs[s], kc, negm[s]);
            float e;
            asm("ex2.approx.ftz.f32 %0, %1;" : "=f"(e) : "f"(t));
            unsigned long long e2, T1, T2, H;
            asm("mov.b64 %0, {%1, %1};" : "=l"(e2) : "r"(__float_as_uint(e)));
            asm("fma.rn.f32x2 %0, %1, %2, %3;" : "=l"(T1) : "l"(qs2[s]),  "l"(A.y), "l"(A.x));
            asm("fma.rn.f32x2 %0, %1, %2, %3;" : "=l"(T2) : "l"(qs2[s]),  "l"(B.y), "l"(B.x));
            asm("fma.rn.f32x2 %0, %1, %2, %3;" : "=l"(H)  : "l"(qsq2[s]), "l"(T2),  "l"(T1));
            asm("fma.rn.f32x2 %0, %1, %2, %0;" : "+l"(acc[s]) : "l"(e2), "l"(H));
        }
        kc += DLT;
    }

    if (grp > 0) {
#pragma unroll
        for (int s = 0; s < ITILE; s++) red[grp - 1][lt][s] = acc[s];
    }
    __syncthreads();

    if (grp == 0) {
#pragma unroll
        for (int s = 0; s < ITILE; s++) {
            unsigned long long t = acc[s];
#pragma unroll
            for (int g = 0; g < NGRP - 1; g++) {
                asm("add.rn.f32x2 %0, %0, %1;" : "+l"(t) : "l"(red[g][lt][s]));
            }
            unsigned int dlo, dhi;
            asm("mov.b64 {%0, %1}, %2;" : "=r"(dlo), "=r"(dhi) : "l"(t));
            out[off + i0 + s * LANES] = __uint_as_float(dhi) / __uint_as_float(dlo);
        }
    }
}

extern "C" void kernel_launch(void* const* d_in, const int* in_sizes, int n_in,
                              void* d_out, int out_size)
{
    const float* x    = (const float*)d_in[0];
    const int*   mask = (const int*)d_in[1];
    const float* Wq   = (const float*)d_in[2];
    const float* Wk   = (const float*)d_in[3];
    const float* Wv   = (const float*)d_in[4];
    float* out = (float*)d_out;

    cudaFuncSetAttribute(gemm_mma, cudaFuncAttributeMaxDynamicSharedMemorySize, GEMM_SMEM);
    gemm_mma<<<384, 256, GEMM_SMEM>>>(x, Wq, Wk, Wv);
    binprep<<<dim3(NCHK, BATCH), 512>>>(mask);
    binmerge<<<BATCH, NBINS>>>();
    attn2<<<dim3(FDIM / (LANES * ITILE), BATCH), NGRP * LANES>>>(out);
}

// round 17
// speedup vs baseline: 1.1643x; 1.0477x over previous
#include <cuda_runtime.h>
#include <cuda_fp16.h>
#include <cstdint>

#define FDIM 2048
#define BATCH 64
#define LOG2E 1.4426950408889634f
#define NSPLIT 4
#define NBINS 128
#define NCHK 4                          // j-chunks per batch row (512 j each)
#define ITILE 4                         // i's per thread in attn2
#define NGRP 8                          // bin-split groups in attn2
#define LANES 64                        // lanes per group in attn2
#define BINS_PER_GRP (NBINS / NGRP)     // 16
#define KMIN_R (-7.0f)
#define RANGE_R 14.0f
#define DLT (RANGE_R / NBINS)
#define INVD (NBINS / RANGE_R)
#define C1T 0.69314718056f     // ln2
#define C2T 0.24022650696f     // ln2^2/2
#define C3T 0.05550410866f     // ln2^3/6

// K-split partial results: g_part[ksplit][0=q,1=k,2=v][b*F]
__device__ float g_part[NSPLIT][3][BATCH * FDIM];

// per-(b,chunk) private bin slices; fully overwritten every call
__device__ float4 g_sliceA[BATCH][NCHK][NBINS];
__device__ float4 g_sliceB[BATCH][NCHK][NBINS];

// split a,b into fp16 hi pair + fp16 lo (residual) pair; a = low half
__device__ __forceinline__ void cvt_split_f16(float a, float b, uint32_t& hi, uint32_t& lo) {
    uint32_t h;
    asm("cvt.rn.f16x2.f32 %0, %1, %2;" : "=r"(h) : "f"(b), "f"(a));
    float2 hf = __half22float2(*(__half2*)&h);   // .x = a-half, .y = b-half
    float la = a - hf.x;
    float lb = b - hf.y;
    asm("cvt.rn.f16x2.f32 %0, %1, %2;" : "=r"(lo) : "f"(lb), "f"(la));
    hi = h;
}

__device__ __forceinline__ uint32_t cvt_f16x2(float a, float b) {
    uint32_t h;
    asm("cvt.rn.f16x2.f32 %0, %1, %2;" : "=r"(h) : "f"(b), "f"(a));
    return h;
}

__device__ __forceinline__ void mma16816f16(float* c, const uint32_t* a, uint32_t b0, uint32_t b1) {
    asm volatile("mma.sync.aligned.m16n8k16.row.col.f32.f16.f16.f32 "
        "{%0,%1,%2,%3}, {%4,%5,%6,%7}, {%8,%9}, {%0,%1,%2,%3};"
        : "+f"(c[0]), "+f"(c[1]), "+f"(c[2]), "+f"(c[3])
        : "r"(a[0]), "r"(a[1]), "r"(a[2]), "r"(a[3]), "r"(b0), "r"(b1));
}

__device__ __forceinline__ void cpa16(uint32_t dst, const void* src) {
    asm volatile("cp.async.cg.shared.global [%0], [%1], 16;" :: "r"(dst), "l"(src));
}

// ============================================================
// Phase 1: warp-MMA GEMM, fp16 asymmetric 2-product split:
// x = xh + xl (fp16), W = fp16 plain; score = xh*W + xl*W.
// (unchanged from R16 — 13.5us measured)
// ============================================================
#define SPITCH 48
#define STG_ARR (64 * SPITCH * 4)
#define STG_PAIR (2 * STG_ARR)
#define NSTAGE 4
#define GEMM_SMEM (NSTAGE * STG_PAIR)  // 98304 B

__global__ __launch_bounds__(256, 2) void gemm_mma(
    const float* __restrict__ x,
    const float* __restrict__ Wq,
    const float* __restrict__ Wk,
    const float* __restrict__ Wv)
{
    extern __shared__ char smem[];
    const uint32_t sb = (uint32_t)__cvta_generic_to_shared(smem);

    const int tid  = threadIdx.x;
    const int wid  = tid >> 5;
    const int lane = tid & 31;

    const int bx   = blockIdx.x;
    const int ks   = bx & 3;
    const int nt   = (bx >> 2) & 31;
    const int wsel = bx >> 7;
    const float* __restrict__ W = (wsel == 0) ? Wq : ((wsel == 1) ? Wk : Wv);
    float* __restrict__ outp = g_part[ks][wsel];
    const int k0 = ks * 512;
    const int n0 = nt * 64;

    const int wm = wid >> 1;
    const int wn = wid & 1;
    const int gid  = lane >> 2;
    const int tidq = lane & 3;

    const int lrow = tid >> 3;
    const int lc16 = tid & 7;
    const float* xsrc0 = x + lrow * FDIM + k0 + lc16 * 4;
    const float* xsrc1 = xsrc0 + 32 * FDIM;
    const float* wsrc0 = W + (n0 + lrow) * FDIM + k0 + lc16 * 4;
    const float* wsrc1 = wsrc0 + 32 * FDIM;
    const uint32_t xdst0 = sb + lrow * 192 + lc16 * 16;
    const uint32_t xdst1 = xdst0 + 32 * 192;
    const uint32_t wdst0 = xdst0 + STG_ARR;
    const uint32_t wdst1 = wdst0 + 32 * 192;

    float acc[4][4];
#pragma unroll
    for (int i = 0; i < 4; i++)
#pragma unroll
        for (int j = 0; j < 4; j++) acc[i][j] = 0.0f;

    const uint32_t a_base = (uint32_t)((wm * 16 + gid) * 192 + tidq * 16);
    const uint32_t b_base = (uint32_t)(STG_ARR + (wn * 32 + gid) * 192 + tidq * 16);

#pragma unroll
    for (int pc = 0; pc < NSTAGE - 1; pc++) {
        const uint32_t so = pc * STG_PAIR;
        const int kf = pc * 32;
        cpa16(so + xdst0, xsrc0 + kf);
        cpa16(so + xdst1, xsrc1 + kf);
        cpa16(so + wdst0, wsrc0 + kf);
        cpa16(so + wdst1, wsrc1 + kf);
        asm volatile("cp.async.commit_group;" ::: "memory");
    }

    for (int c = 0; c < 16; c++) {
        asm volatile("cp.async.wait_group 2;" ::: "memory");
        __syncthreads();

        const int nc = c + NSTAGE - 1;
        if (nc < 16) {
            const uint32_t so = (nc & (NSTAGE - 1)) * STG_PAIR;
            const int kf = nc * 32;
            cpa16(so + xdst0, xsrc0 + kf);
            cpa16(so + xdst1, xsrc1 + kf);
            cpa16(so + wdst0, wsrc0 + kf);
            cpa16(so + wdst1, wsrc1 + kf);
        }
        asm volatile("cp.async.commit_group;" ::: "memory");

        const uint32_t slot = (c & (NSTAGE - 1)) * STG_PAIR;
        const uint32_t aa = sb + slot + a_base;
        const uint32_t bb = sb + slot + b_base;

#pragma unroll
        for (int kstep = 0; kstep < 2; kstep++) {
            const uint32_t kb = kstep * 64;
            float4 A0, A1;
            asm volatile("ld.shared.v4.f32 {%0,%1,%2,%3}, [%4];"
                : "=f"(A0.x), "=f"(A0.y), "=f"(A0.z), "=f"(A0.w) : "r"(aa + kb));
            asm volatile("ld.shared.v4.f32 {%0,%1,%2,%3}, [%4];"
                : "=f"(A1.x), "=f"(A1.y), "=f"(A1.z), "=f"(A1.w) : "r"(aa + kb + 8 * 192));
            uint32_t ah[4], al[4];
            cvt_split_f16(A0.x, A0.y, ah[0], al[0]);
            cvt_split_f16(A1.x, A1.y, ah[1], al[1]);
            cvt_split_f16(A0.z, A0.w, ah[2], al[2]);
            cvt_split_f16(A1.z, A1.w, ah[3], al[3]);

#pragma unroll
            for (int t = 0; t < 4; t++) {
                float4 B;
                asm volatile("ld.shared.v4.f32 {%0,%1,%2,%3}, [%4];"
                    : "=f"(B.x), "=f"(B.y), "=f"(B.z), "=f"(B.w)
                    : "r"(bb + kb + t * 8 * 192));
                const uint32_t b0 = cvt_f16x2(B.x, B.y);
                const uint32_t b1 = cvt_f16x2(B.z, B.w);
                mma16816f16(acc[t], ah, b0, b1);    // xh * W
                mma16816f16(acc[t], al, b0, b1);    // xl * W
            }
        }
    }

    const int orow = wm * 16 + (lane >> 2);
    const int ocol = n0 + wn * 32 + (lane & 3) * 2;
#pragma unroll
    for (int t = 0; t < 4; t++) {
        const int col = ocol + t * 8;
        *(float2*)&outp[orow * FDIM + col]       = make_float2(acc[t][0], acc[t][1]);
        *(float2*)&outp[(orow + 8) * FDIM + col] = make_float2(acc[t][2], acc[t][3]);
    }
}

// ============================================================
// Phase 2a: parallel binning, grid (NCHK, BATCH), 512 threads.
// ============================================================
__global__ __launch_bounds__(512) void binprep(const int* __restrict__ mask)
{
    __shared__ __align__(16) float4 sA[NBINS];
    __shared__ __align__(16) float4 sB[NBINS];

    const int b   = blockIdx.y;
    const int ch  = blockIdx.x;
    const int tid = threadIdx.x;
    const int off = b * FDIM;
    const int j   = ch * 512 + tid;

    if (tid < NBINS) {
        sA[tid] = make_float4(0.f, 0.f, 0.f, 0.f);
        sB[tid] = make_float4(0.f, 0.f, 0.f, 0.f);
    }
    __syncthreads();

    const int m = mask[off + j];
    if (m) {
        float kv = 0.0f, vv = 0.0f;
#pragma unroll
        for (int sp = 0; sp < NSPLIT; sp++) {
            kv += g_part[sp][1][off + j];
            vv += g_part[sp][2][off + j];
        }
        int bi = (int)((kv - KMIN_R) * INVD);
        bi = bi < 0 ? 0 : (bi > NBINS - 1 ? NBINS - 1 : bi);
        const float d  = kv - (KMIN_R + (bi + 0.5f) * DLT);
        const float d1 = C1T * d;
        const float d2 = C2T * d * d;
        const float d3 = C3T * d * d * d;
        atomicAdd(&sA[bi].x, 1.0f);
        atomicAdd(&sA[bi].y, vv);
        atomicAdd(&sA[bi].z, d1);
        atomicAdd(&sA[bi].w, d1 * vv);
        atomicAdd(&sB[bi].x, d2);
        atomicAdd(&sB[bi].y, d2 * vv);
        atomicAdd(&sB[bi].z, d3);
        atomicAdd(&sB[bi].w, d3 * vv);
    }
    __syncthreads();

    if (tid < NBINS) {
        g_sliceA[b][ch][tid] = sA[tid];
        g_sliceB[b][ch][tid] = sB[tid];
    }
}

// ============================================================
// Phase 2b: attended[b,i]. Block = 512 thr = 8 groups x 64
// lanes; slice-merge fused into bin staging (binmerge kernel
// removed). Group g handles bins [16g, 16g+16) for ITILE=4
// i's; partials merged via smem, group 0 divides and stores.
// Estrin: H = (S0 + qs*S1) + qs^2*(S2 + qs*S3); packed f32x2.
// ============================================================
__global__ __launch_bounds__(NGRP * LANES) void attn2(float* __restrict__ out)
{
    __shared__ __align__(16) float4 sAA[NBINS];
    __shared__ __align__(16) float4 sBB[NBINS];
    __shared__ unsigned long long red[NGRP - 1][LANES][ITILE];

    const int b   = blockIdx.y;
    const int tid = threadIdx.x;
    const int grp = tid >> 6;
    const int lt  = tid & 63;
    const int off = b * FDIM;

    // fused slice merge: thread t owns bin t
    if (tid < NBINS) {
        float4 a = make_float4(0.f, 0.f, 0.f, 0.f);
        float4 bb = make_float4(0.f, 0.f, 0.f, 0.f);
#pragma unroll
        for (int ch = 0; ch < NCHK; ch++) {
            float4 va = g_sliceA[b][ch][tid];
            float4 vb = g_sliceB[b][ch][tid];
            a.x += va.x; a.y += va.y; a.z += va.z; a.w += va.w;
            bb.x += vb.x; bb.y += vb.y; bb.z += vb.z; bb.w += vb.w;
        }
        sAA[tid] = a;
        sBB[tid] = bb;
    }
    __syncthreads();

    const int i0 = blockIdx.x * (LANES * ITILE) + lt;

    float qs[ITILE], negm[ITILE];
    unsigned long long qs2[ITILE], qsq2[ITILE], acc[ITILE];
#pragma unroll
    for (int s = 0; s < ITILE; s++) {
        float qraw = 0.0f;
#pragma unroll
        for (int sp = 0; sp < NSPLIT; sp++) qraw += g_part[sp][0][off + i0 + s * LANES];
        qs[s]   = qraw * LOG2E;
        negm[s] = -7.0f * fabsf(qs[s]);
        const float qq = qs[s] * qs[s];
        asm("mov.b64 %0, {%1, %1};" : "=l"(qs2[s])  : "r"(__float_as_uint(qs[s])));
        asm("mov.b64 %0, {%1, %1};" : "=l"(qsq2[s]) : "r"(__float_as_uint(qq)));
        acc[s] = 0ull;
    }

    const int pbase = grp * BINS_PER_GRP;
    float kc = KMIN_R + (pbase + 0.5f) * DLT;
#pragma unroll 2
    for (int p = 0; p < BINS_PER_GRP; p++) {
        ulonglong2 A = *(const ulonglong2*)&sAA[pbase + p];
        ulonglong2 B = *(const ulonglong2*)&sBB[pbase + p];
#pragma unroll
        for (int s = 0; s < ITILE; s++) {
            float t = fmaf(qs[s], kc, negm[s]);
            float e;
            asm("ex2.approx.ftz.f32 %0, %1;" : "=f"(e) : "f"(t));
            unsigned long long e2, T1, T2, H;
            asm("mov.b64 %0, {%1, %1};" : "=l"(e2) : "r"(__float_as_uint(e)));
            asm("fma.rn.f32x2 %0, %1, %2, %3;" : "=l"(T1) : "l"(qs2[s]),  "l"(A.y), "l"(A.x));
            asm("fma.rn.f32x2 %0, %1, %2, %3;" : "=l"(T2) : "l"(qs2[s]),  "l"(B.y), "l"(B.x));
            asm("fma.rn.f32x2 %0, %1, %2, %3;" : "=l"(H)  : "l"(qsq2[s]), "l"(T2),  "l"(T1));
            asm("fma.rn.f32x2 %0, %1, %2, %0;" : "+l"(acc[s]) : "l"(e2), "l"(H));
        }
        kc += DLT;
    }

    if (grp > 0) {
#pragma unroll
        for (int s = 0; s < ITILE; s++) red[grp - 1][lt][s] = acc[s];
    }
    __syncthreads();

    if (grp == 0) {
#pragma unroll
        for (int s = 0; s < ITILE; s++) {
            unsigned long long t = acc[s];
#pragma unroll
            for (int g = 0; g < NGRP - 1; g++) {
                asm("add.rn.f32x2 %0, %0, %1;" : "+l"(t) : "l"(red[g][lt][s]));
            }
            unsigned int dlo, dhi;
            asm("mov.b64 {%0, %1}, %2;" : "=r"(dlo), "=r"(dhi) : "l"(t));
            out[off + i0 + s * LANES] = __uint_as_float(dhi) / __uint_as_float(dlo);
        }
    }
}

extern "C" void kernel_launch(void* const* d_in, const int* in_sizes, int n_in,
                              void* d_out, int out_size)
{
    const float* x    = (const float*)d_in[0];
    const int*   mask = (const int*)d_in[1];
    const float* Wq   = (const float*)d_in[2];
    const float* Wk   = (const float*)d_in[3];
    const float* Wv   = (const float*)d_in[4];
    float* out = (float*)d_out;

    cudaFuncSetAttribute(gemm_mma, cudaFuncAttributeMaxDynamicSharedMemorySize, GEMM_SMEM);
    gemm_mma<<<384, 256, GEMM_SMEM>>>(x, Wq, Wk, Wv);
    binprep<<<dim3(NCHK, BATCH), 512>>>(mask);
    attn2<<<dim3(FDIM / (LANES * ITILE), BATCH), NGRP * LANES>>>(out);
}